// round 2
// baseline (speedup 1.0000x reference)
#include <cuda_runtime.h>

#define ROWS 84
#define SLEN 131072
#define BPR 16                    // blocks per row
#define THREADS 256
#define CHUNK (SLEN / BPR)        // 8192 elements
#define ITERS (CHUNK / (THREADS * 4))  // 8 float4 iterations per thread

// scratch: per (row, chunk) partial sums for ST0-side and ST1-side
__device__ float g_partial[ROWS * BPR * 2];

__device__ __forceinline__ float sigf(float x) {
    return __fdividef(1.0f, 1.0f + __expf(-x));
}

__global__ __launch_bounds__(THREADS)
void reduce_kernel(const float* __restrict__ ST0, const float* __restrict__ W0,
                   const float* __restrict__ ST1, const float* __restrict__ W1,
                   const float* __restrict__ BEV, const float* __restrict__ BEV_p,
                   const float* __restrict__ B) {
    const int row = blockIdx.y;
    const int chunk = blockIdx.x;
    const float b = B[0];
    const float bias = fmaxf(BEV_p[0], 0.0f) * BEV[0];
    const float bb = b * bias;   // sig(b*st + bb)

    const size_t base = (size_t)row * SLEN + (size_t)chunk * CHUNK;
    const float4* st0 = (const float4*)(ST0 + base);
    const float4* w0  = (const float4*)(W0 + base);
    const float4* st1 = (const float4*)(ST1 + base);
    const float4* w1  = (const float4*)(W1 + base);

    float s0 = 0.0f, s1 = 0.0f;
    #pragma unroll
    for (int it = 0; it < ITERS; ++it) {
        const int idx = it * THREADS + threadIdx.x;
        float4 a0 = st0[idx];
        float4 c0 = w0[idx];
        float4 a1 = st1[idx];
        float4 c1 = w1[idx];
        s0 += sigf(fmaf(b, a0.x, bb)) * c0.x;
        s0 += sigf(fmaf(b, a0.y, bb)) * c0.y;
        s0 += sigf(fmaf(b, a0.z, bb)) * c0.z;
        s0 += sigf(fmaf(b, a0.w, bb)) * c0.w;
        s1 += sigf(fmaf(b, a1.x, bb)) * c1.x;
        s1 += sigf(fmaf(b, a1.y, bb)) * c1.y;
        s1 += sigf(fmaf(b, a1.z, bb)) * c1.z;
        s1 += sigf(fmaf(b, a1.w, bb)) * c1.w;
    }

    // block reduction
    #pragma unroll
    for (int o = 16; o > 0; o >>= 1) {
        s0 += __shfl_down_sync(0xFFFFFFFFu, s0, o);
        s1 += __shfl_down_sync(0xFFFFFFFFu, s1, o);
    }
    __shared__ float sh0[THREADS / 32], sh1[THREADS / 32];
    const int warp = threadIdx.x >> 5, lane = threadIdx.x & 31;
    if (lane == 0) { sh0[warp] = s0; sh1[warp] = s1; }
    __syncthreads();
    if (threadIdx.x == 0) {
        float t0 = 0.0f, t1 = 0.0f;
        #pragma unroll
        for (int w = 0; w < THREADS / 32; ++w) { t0 += sh0[w]; t1 += sh1[w]; }
        const int slot = (row * BPR + chunk) * 2;
        g_partial[slot]     = t0;
        g_partial[slot + 1] = t1;
    }
}

__device__ __forceinline__ void build_probs(const float* __restrict__ logits, float* P) {
    float l0 = logits[0], l1 = logits[1], l2 = logits[2], l3 = logits[3];
    float mx = fmaxf(fmaxf(l0, l1), fmaxf(l2, l3));
    float e0 = __expf(l0 - mx), e1 = __expf(l1 - mx),
          e2 = __expf(l2 - mx), e3 = __expf(l3 - mx);
    float inv = __fdividef(1.0f, e0 + e1 + e2 + e3);
    float p[4] = {e0 * inv, e1 * inv, e2 * inv, e3 * inv};
    int idx = 0;
    #pragma unroll
    for (int i = 0; i < 4; ++i) {
        P[idx++] = p[i];
        #pragma unroll
        for (int j = 0; j < 4; ++j) {
            float pij = p[i] * p[j];
            P[idx++] = pij;
            #pragma unroll
            for (int k = 0; k < 4; ++k)
                P[idx++] = pij * p[k];
        }
    }
}

__global__ void finalize_kernel(const float* __restrict__ probs0,
                                const float* __restrict__ probs1,
                                const float* __restrict__ probs2,
                                const float* __restrict__ probs3,
                                const float* __restrict__ probs4,
                                float* __restrict__ out) {
    __shared__ float tmp0[ROWS], tmp1[ROWS];
    const int t = threadIdx.x;
    if (t < ROWS) {
        float a = 0.0f, c = 0.0f;
        #pragma unroll
        for (int k = 0; k < BPR; ++k) {
            const int slot = (t * BPR + k) * 2;
            a += g_partial[slot];
            c += g_partial[slot + 1];
        }
        tmp0[t] = a;
        tmp1[t] = c;
    }
    __syncthreads();
    if (t == 0) {
        const float* logits[5] = {probs0, probs1, probs2, probs3, probs4};
        float acc = 0.0f;
        for (int m = 0; m < 5; ++m) {
            float P[ROWS];
            build_probs(logits[m], P);
            const float* tmp = (m == 0) ? tmp0 : tmp1;
            float v = 0.0f;
            #pragma unroll
            for (int i = 0; i < ROWS; ++i) v += P[i] * tmp[i];
            acc += v;
        }
        out[0] = acc * 0.2f;
    }
}

extern "C" void kernel_launch(void* const* d_in, const int* in_sizes, int n_in,
                              void* d_out, int out_size) {
    const float* BEV   = (const float*)d_in[0];
    const float* ST0   = (const float*)d_in[1];
    const float* W0    = (const float*)d_in[2];
    const float* ST1   = (const float*)d_in[3];
    const float* W1    = (const float*)d_in[4];
    const float* p0    = (const float*)d_in[5];
    const float* p1    = (const float*)d_in[6];
    const float* p2    = (const float*)d_in[7];
    const float* p3    = (const float*)d_in[8];
    const float* p4    = (const float*)d_in[9];
    const float* BEV_p = (const float*)d_in[10];
    const float* B     = (const float*)d_in[11];
    float* out = (float*)d_out;

    dim3 grid(BPR, ROWS);
    reduce_kernel<<<grid, THREADS>>>(ST0, W0, ST1, W1, BEV, BEV_p, B);
    finalize_kernel<<<1, 128>>>(p0, p1, p2, p3, p4, out);
}